// round 13
// baseline (speedup 1.0000x reference)
#include <cuda_runtime.h>
#include <math_constants.h>

// Roi_61564061221098 round 13: R12 (NHWC) + overlap-dedupe register carries.
//  - column carry: adjacent pw bins share <=1 boundary column; carry its
//    colmax/last-row value instead of re-reading.
//  - row carry: adjacent ph bins share <=1 boundary row; carry each bin's
//    max over row (h1-1) and seed the next ph bin, starting reads at h0+1.
//  Both carries read the exact bin rectangles -> bit-identical results.

#define NC    512
#define FH    50
#define FW    68
#define NPOS  (FH * FW)          // 3400
#define PP    7
#define SCALE 0.0625f
#define NEG_INF (-CUDART_INF_F)
#define SSTR  517                // sbin row stride (coprime with 32 banks)
#define NB0   28                 // bins in half 0 (ph 0..3)
#define NB1   21                 // bins in half 1 (ph 4..6)
#define SMEMB (NB0 * SSTR * 4)   // 57,904 B

__device__ float4 g_nhwc4[4 * NPOS * (NC / 4)];   // 27.85 MB scratch
// per-roi record: [0]=image n, [3..9] = hs | he<<8 | ws<<16 | we<<24 (absolute)
__device__ __align__(16) int g_rec[4096 * 16];

__global__ void transpose_kernel(const float* __restrict__ x)
{
    __shared__ float tile[32][33];
    const int n  = blockIdx.z;
    const int c0 = blockIdx.y * 32;
    const int p0 = blockIdx.x * 32;
    const int tx = threadIdx.x, ty = threadIdx.y;    // block (32, 8)
    float* __restrict__ dst = (float*)g_nhwc4;

#pragma unroll
    for (int dy = 0; dy < 32; dy += 8) {
        const int c = c0 + ty + dy;
        const int p = p0 + tx;
        tile[ty + dy][tx] = (p < NPOS) ? x[(n * NC + c) * NPOS + p] : 0.0f;
    }
    __syncthreads();
#pragma unroll
    for (int dy = 0; dy < 32; dy += 8) {
        const int p = p0 + ty + dy;
        if (p < NPOS) dst[((size_t)n * NPOS + p) * NC + c0 + tx] = tile[tx][ty + dy];
    }
}

__global__ void roi_prep(const float* __restrict__ rois,
                         const int*   __restrict__ ridx, int R)
{
    int r = blockIdx.x * blockDim.x + threadIdx.x;
    if (r >= R) return;

    const float y1 = rois[r * 4 + 0];
    const float x1 = rois[r * 4 + 1];
    const float y2 = rois[r * 4 + 2];
    const float x2 = rois[r * 4 + 3];
    const float rb0 = rintf(__fmul_rn(x1, SCALE));
    const float rb1 = rintf(__fmul_rn(y1, SCALE));
    const float rb2 = rintf(__fmul_rn(x2, SCALE));
    const float rb3 = rintf(__fmul_rn(y2, SCALE));
    const float roiw = fmaxf(__fadd_rn(__fsub_rn(rb2, rb0), 1.0f), 1.0f);
    const float roih = fmaxf(__fadd_rn(__fsub_rn(rb3, rb1), 1.0f), 1.0f);
    const float R7 = (float)(1.0 / 7.0);          // XLA: x/7 -> x * fl(1/7)
    const float bw = __fmul_rn(roiw, R7);
    const float bh = __fmul_rn(roih, R7);

    int* rec = g_rec + r * 16;
    rec[0] = ridx[r];
#pragma unroll
    for (int p = 0; p < PP; p++) {
        const float fp  = (float)p;
        const float fp1 = (float)(p + 1);
        int hs = (int)fminf(fmaxf(__fadd_rn(floorf(__fmul_rn(fp,  bh)), rb1), 0.0f), (float)FH);
        int he = (int)fminf(fmaxf(__fadd_rn(ceilf (__fmul_rn(fp1, bh)), rb1), 0.0f), (float)FH);
        int ws = (int)fminf(fmaxf(__fadd_rn(floorf(__fmul_rn(fp,  bw)), rb0), 0.0f), (float)FW);
        int we = (int)fminf(fmaxf(__fadd_rn(ceilf (__fmul_rn(fp1, bw)), rb0), 0.0f), (float)FW);
        rec[3 + p] = hs | (he << 8) | (ws << 16) | (we << 24);
    }
}

__device__ __forceinline__ void fmax4(float4& a, const float4 b)
{
    a.x = fmaxf(a.x, b.x); a.y = fmaxf(a.y, b.y);
    a.z = fmaxf(a.z, b.z); a.w = fmaxf(a.w, b.w);
}

__global__ __launch_bounds__(256, 3)
void roi_pool(float* __restrict__ out, int R)
{
    extern __shared__ float sbin[];                 // [nb][SSTR]

    const int bid  = blockIdx.x;
    const int r    = bid >> 1;
    const int half = bid & 1;
    const int tid  = threadIdx.x;
    const int warp = tid >> 5;
    const int lane = tid & 31;
    const int chid = warp & 3;          // 128-channel slice
    const int pwg  = warp >> 2;         // 0: pw 0-3, 1: pw 4-6

    int v = 0;
    if (lane < 16) v = g_rec[r * 16 + lane];
    const int n = __shfl_sync(0xffffffffu, v, 0);

    // float4 lane base: channel chid*128 + lane*4; position stride = 128 float4
    const float4* __restrict__ base =
        g_nhwc4 + (size_t)n * NPOS * (NC / 4) + chid * 32 + lane;

    const int npw = pwg ? 3 : 4;
    const int pw0 = pwg * 4;
    int wsA[4], weA[4];
#pragma unroll
    for (int i = 0; i < 4; i++) {
        const int qk = __shfl_sync(0xffffffffu, v, 3 + pw0 + (i < npw ? i : 0));
        wsA[i] = (qk >> 16) & 0xff;
        weA[i] = (qk >> 24) & 0xff;
    }
    const int phN = half ? 3 : 4;
    const int ph0 = half ? 4 : 0;

    const float4 NI4 = make_float4(NEG_INF, NEG_INF, NEG_INF, NEG_INF);
    float4 rowc[4] = {NI4, NI4, NI4, NI4};   // per-bin max over row (prevh1-1)
    int prevh1 = -1000;

    for (int phi = 0; phi < phN; phi++) {
        const int pk = __shfl_sync(0xffffffffu, v, 3 + ph0 + phi);
        const int h0 = pk & 0xff;
        const int h1 = (pk >> 8) & 0xff;
        const bool hnon = h0 < h1;
        const bool seed = hnon && (h0 == prevh1 - 1);   // boundary row carried
        const int  hb   = seed ? h0 + 1 : h0;           // rows actually read

        int lastw = -1000;                   // column carry (within this ph)
        float4 colc = NI4, tlc = NI4;        // colmax over [hb,h1), value@h1-1

#pragma unroll
        for (int pwi = 0; pwi < 4; pwi++) {
            if (pwi >= npw) break;
            const int ws = wsA[pwi], we = weA[pwi];
            float4 acc = NI4;                // bin result
            float4 rc  = NI4;                // bin max over row h1-1 (next carry)

            if (hnon && ws < we) {
                if (seed) acc = rowc[pwi];   // boundary row, this bin's columns
                if (hb < h1) {
                    int w = ws;
                    if (w == lastw) {        // overlap column already computed
                        fmax4(acc, colc);
                        fmax4(rc, tlc);
                        w++;
                    }
                    for (; w < we; w++) {
                        const float4* p = base + (hb * FW + w) * (NC / 4);
                        float4 tl = *p;                  // row hb
                        float4 m  = tl;
                        for (int h = hb + 1; h < h1; h++) {
                            p += FW * (NC / 4);
                            tl = *p;                     // ends at row h1-1
                            fmax4(m, tl);
                        }
                        fmax4(acc, m);
                        fmax4(rc, tl);
                        colc = m; tlc = tl; lastw = w;
                    }
                } else {
                    rc = rowc[pwi];          // bin == the seeded row only
                }
            }
            if (hnon) rowc[pwi] = rc;

            // empty bin -> 0.0 per reference isfinite rule
            const int b = phi * PP + pw0 + pwi;          // local bin index
            float* s = sbin + b * SSTR + chid * 128 + lane * 4;
            s[0] = (acc.x == NEG_INF) ? 0.0f : acc.x;
            s[1] = (acc.y == NEG_INF) ? 0.0f : acc.y;
            s[2] = (acc.z == NEG_INF) ? 0.0f : acc.z;
            s[3] = (acc.w == NEG_INF) ? 0.0f : acc.w;
        }
        if (hnon) prevh1 = h1;
    }
    __syncthreads();

    // flush: out[r][ch][half ? 28+b : b]
    const size_t ob = (size_t)r * (NC * 49) + (half ? NB0 : 0);
    if (half == 0) {
        for (int i = tid; i < NB0 * NC; i += 256) {
            const int ch = i / NB0;
            const int b  = i - ch * NB0;
            out[ob + ch * 49 + b] = sbin[b * SSTR + ch];
        }
    } else {
        for (int i = tid; i < NB1 * NC; i += 256) {
            const int ch = i / NB1;
            const int b  = i - ch * NB1;
            out[ob + ch * 49 + b] = sbin[b * SSTR + ch];
        }
    }
}

extern "C" void kernel_launch(void* const* d_in, const int* in_sizes, int n_in,
                              void* d_out, int out_size)
{
    const float* x    = (const float*)d_in[0];
    const float* rois = (const float*)d_in[1];
    const int*   ridx = (const int*)d_in[2];
    float*       out  = (float*)d_out;
    const int R = in_sizes[2];

    cudaFuncSetAttribute(roi_pool, cudaFuncAttributeMaxDynamicSharedMemorySize,
                         SMEMB);

    dim3 tgrid((NPOS + 31) / 32, NC / 32, 4);
    transpose_kernel<<<tgrid, dim3(32, 8)>>>(x);
    roi_prep<<<(R + 255) / 256, 256>>>(rois, ridx, R);
    roi_pool<<<R * 2, 256, SMEMB>>>(out, R);
}